// round 10
// baseline (speedup 1.0000x reference)
#include <cuda_runtime.h>
#include <cuda_bf16.h>

typedef unsigned long long u64;

// Problem constants
#define B_   16
#define K_   256
#define T_   64
#define D_   128
// e = C_LIN*(P+Q) + C_ABS*sum_d a_d*|u+vb| + bias   (alpha = 0.2)
#define C_LIN 0.6f
#define C_ABS 0.4f
#define ABSMASK2 0x7FFFFFFF7FFFFFFFULL

__device__ __forceinline__ u64 addx2(u64 a, u64 b) {
    u64 r; asm("add.rn.f32x2 %0,%1,%2;" : "=l"(r) : "l"(a), "l"(b)); return r;
}
__device__ __forceinline__ u64 fmax2p(u64 a, u64 b, u64 c) {
    u64 r; asm("fma.rn.f32x2 %0,%1,%2,%3;" : "=l"(r) : "l"(a), "l"(b), "l"(c)); return r;
}
__device__ __forceinline__ u64 dup2(float v) {
    u64 r; asm("mov.b64 %0, {%1, %1};" : "=l"(r) : "f"(v)); return r;
}
__device__ __forceinline__ u64 pack2(float lo, float hi) {
    u64 r; asm("mov.b64 %0, {%1, %2};" : "=l"(r) : "f"(lo), "f"(hi)); return r;
}
__device__ __forceinline__ float lo32(u64 v) { return __uint_as_float((unsigned)v); }
__device__ __forceinline__ float hi32(u64 v) { return __uint_as_float((unsigned)(v >> 32)); }

// Scratch (device globals: allocation-free rule)
__device__ float g_U [B_*K_*D_];   // u[b,k,d]
__device__ float g_Vb[B_*K_*D_];   // v[b,k,d] + b_lin[d]
__device__ float g_P [B_*K_];      // sum_d a_d * u
__device__ float g_Q [B_*K_];      // sum_d a_d * vb

// ---------------------------------------------------------------------------
// Kernel A v3: lane = row (32 rows/block), warp = 16 output columns.
// x transposed in smem (scalar conflict-free loads), W read BROADCAST.
// Writeback through an smem transpose (stride 257) for coalesced STG.
// 128 blocks x 512 threads.
// ---------------------------------------------------------------------------
#define WS_STRIDE 68
#define XT_STRIDE 33
#define OB_STRIDE 257
#define KA_W_F    (256*WS_STRIDE)            // 17408
#define KA_XT_OFF (KA_W_F)                   // 64 x 33 = 2112
#define KA_AS_OFF (KA_XT_OFF + 64*XT_STRIDE) // 19520
#define KA_BL_OFF (KA_AS_OFF + 128)          // 19648
#define KA_RP_OFF (KA_BL_OFF + 128)          // 19776  (8 x 33)
#define KA_RQ_OFF (KA_RP_OFF + 8*33)         // 20040
#define KA_SMEM_FLOATS (KA_RQ_OFF + 8*33)    // 20304 floats = 81216 B

__global__ void __launch_bounds__(512)
kA(const float* __restrict__ x, const float* __restrict__ W,
   const float* __restrict__ b_lin, const float* __restrict__ a)
{
    extern __shared__ float sm[];
    float* Ws   = sm;                 // Wr[c][t], c = 0..255 (c<128 -> W1, else W2)
    float* xst  = sm + KA_XT_OFF;     // xst[k*33 + row]
    float* asA  = sm + KA_AS_OFF;
    float* bls  = sm + KA_BL_OFF;
    float* redP = sm + KA_RP_OFF;
    float* redQ = sm + KA_RQ_OFF;
    float* outB = sm;                 // overlay on Ws after main loop

    const int tid  = threadIdx.x;
    const int row0 = blockIdx.x * 32;

    for (int idx = tid; idx < 256*64; idx += 512) {
        const int n = idx >> 6, t = idx & 63;
        Ws[n*WS_STRIDE + t] = (n < 128) ? W[n*128 + t] : W[(n-128)*128 + 64 + t];
    }
    for (int idx = tid; idx < 32*64; idx += 512) {
        const int r = idx >> 6, k = idx & 63;
        xst[k*XT_STRIDE + r] = x[(row0 + r)*T_ + k];
    }
    if (tid < 128) asA[tid] = a[tid];
    else if (tid >= 256 && tid < 384) bls[tid - 256] = b_lin[tid - 256];
    __syncthreads();

    const int l  = tid & 31;       // lane = local row
    const int w  = tid >> 5;       // warp -> cols [16w, 16w+16)
    const int c0 = w * 16;

    u64 acc[16];
    #pragma unroll
    for (int cc = 0; cc < 16; cc++) acc[cc] = 0ull;

    #pragma unroll 4
    for (int k4 = 0; k4 < 16; k4++) {
        const float x0 = xst[(4*k4 + 0)*XT_STRIDE + l];
        const float x1 = xst[(4*k4 + 1)*XT_STRIDE + l];
        const float x2 = xst[(4*k4 + 2)*XT_STRIDE + l];
        const float x3 = xst[(4*k4 + 3)*XT_STRIDE + l];
        const u64 xp01 = pack2(x0, x1);
        const u64 xp23 = pack2(x2, x3);
        #pragma unroll
        for (int cc = 0; cc < 16; cc++) {
            const ulonglong2 wv = *(const ulonglong2*)(Ws + (c0 + cc)*WS_STRIDE + 4*k4);
            acc[cc] = fmax2p(xp01, wv.x, acc[cc]);
            acc[cc] = fmax2p(xp23, wv.y, acc[cc]);
        }
    }
    __syncthreads();   // all Ws reads done before outB overlay

    // finalize: add b_lin for V-cols, P/Q partials, stash to outB (stride 257)
    {
        float pq = 0.f;
        const bool isV = (w >= 8);
        #pragma unroll
        for (int cc = 0; cc < 16; cc++) {
            const int c  = c0 + cc;
            float sv = lo32(acc[cc]) + hi32(acc[cc]);
            if (isV) sv += bls[c - 128];
            outB[l*OB_STRIDE + c] = sv;
            pq = fmaf(asA[c & 127], sv, pq);
        }
        if (isV) redQ[(w - 8)*33 + l] = pq;
        else     redP[w*33 + l]       = pq;
    }
    __syncthreads();

    // P/Q combine
    if (tid < 32) {
        float p = 0.f;
        #pragma unroll
        for (int ww = 0; ww < 8; ww++) p += redP[ww*33 + tid];
        g_P[row0 + tid] = p;
    } else if (tid < 64) {
        const int r = tid - 32;
        float q = 0.f;
        #pragma unroll
        for (int ww = 0; ww < 8; ww++) q += redQ[ww*33 + r];
        g_Q[row0 + r] = q;
    }

    // coalesced writeback
    for (int idx = tid; idx < 32*256; idx += 512) {
        const int r = idx >> 8, c = idx & 255;
        const float val = outB[r*OB_STRIDE + c];
        if (c < 128) g_U [(row0 + r)*D_ + c]       = val;
        else         g_Vb[(row0 + r)*D_ + c - 128] = val;
    }
}

// ---------------------------------------------------------------------------
// Kernel B: transposed e-loop (32 warps), no-max softmax, deferred
// normalization, split epilogue.  Grid (8,16) x 1024 threads.
// ---------------------------------------------------------------------------
#define VBS_F   (K_*132)                   // 33792
#define US_OFF  (VBS_F)                    // 33792
#define AS_OFF  (US_OFF + 32*132)          // 38016
#define QS_OFF  (AS_OFF + 128)             // 38144
#define PS_OFF  (QS_OFF + 256)             // 38400
#define SR_OFF  (PS_OFF + 32)              // 38432  (32*32)
#define WSC_OFF (SR_OFF + 1024)            // 39456
#define KB_SMEM_FLOATS (WSC_OFF + K_*36)   // 48672 floats = 194688 B
// overlays inside the dead Vbs region (post e-loop):
#define HR_OFF  16384                      // hred: 32i*4c*33 u64 = 8448 floats

__global__ void __launch_bounds__(1024)
kB(const float* __restrict__ x, const float* __restrict__ a,
   const float* __restrict__ bias, float* __restrict__ out)
{
    extern __shared__ float sm[];
    float* Vbs  = sm;
    float* Us   = sm + US_OFF;
    float* as_  = sm + AS_OFF;
    float* Qs   = sm + QS_OFF;
    float* Ps   = sm + PS_OFF;
    float* sred = sm + SR_OFF;
    float* ws   = sm + WSC_OFF;  // raw exp weights, ws[j*36 + il]

    const int tid = threadIdx.x;
    const int b   = blockIdx.y;
    const int igbase = blockIdx.x * 32;

    // ---- stage Vb[b], 32 U rows, a, Q, P ----
    {
        const float4* vg4  = (const float4*)g_Vb + b * (K_*D_/4);
        float4*       vbs4 = (float4*)Vbs;
        for (int idx = tid; idx < K_*D_/4; idx += 1024) {
            const int j = idx >> 5, c = idx & 31;
            vbs4[j*33 + c] = vg4[idx];
        }
        const float4* ug4 = (const float4*)g_U + (b*K_ + igbase) * (D_/4);
        float4*       us4 = (float4*)Us;
        for (int idx = tid; idx < 32*D_/4; idx += 1024) {
            const int il = idx >> 5, c = idx & 31;
            us4[il*33 + c] = ug4[idx];
        }
        if (tid < 128) as_[tid] = a[tid];
        else if (tid >= 256 && tid < 512) Qs[tid - 256] = g_Q[b*K_ + tid - 256];
        else if (tid >= 512 && tid < 544) Ps[tid - 512] = g_P[b*K_ + igbase + tid - 512];
    }

    const int w  = tid >> 5;
    const int l  = tid & 31;           // lane = local i row
    const int j0 = w * 8;              // warp's j chunk (8 rows)

    // bias prefetch (latency hidden under barrier + e-loop)
    const float4* brow4 = (const float4*)(bias + (igbase + l)*K_ + j0);
    const float4 bv0 = __ldg(brow4);
    const float4 bv1 = __ldg(brow4 + 1);

    __syncthreads();   // B1

    // ---- e-loop: acc[jj] = packed sum_d a_d * |u_{l,d} + vb_{j0+jj,d}| ----
    u64 acc[8];
    #pragma unroll
    for (int jj = 0; jj < 8; jj++) acc[jj] = 0ull;

    {
        const ulonglong2* vbs2 = (const ulonglong2*)Vbs;   // row stride 33
        const ulonglong2* us2  = (const ulonglong2*)Us;
        const ulonglong2* a2   = (const ulonglong2*)as_;
        for (int dc = 0; dc < 32; dc++) {
            const ulonglong2 uv = us2[l*33 + dc];          // lane-varying
            const ulonglong2 av = a2[dc];                  // broadcast
            ulonglong2 vv[8];
            #pragma unroll
            for (int jj = 0; jj < 8; jj++) vv[jj] = vbs2[(j0 + jj)*33 + dc];
            #pragma unroll
            for (int jj = 0; jj < 8; jj++) {
                u64 z;
                z = addx2(uv.x, vv[jj].x); acc[jj] = fmax2p(av.x, z & ABSMASK2, acc[jj]);
                z = addx2(uv.y, vv[jj].y); acc[jj] = fmax2p(av.y, z & ABSMASK2, acc[jj]);
            }
        }
    }

    // ---- e -> raw exp weights (no max subtraction; |e| ~ O(15), fp32-safe),
    //      warp-partial sums, stash raw weights ----
    {
        const float P = Ps[l];
        const float bb[8] = {bv0.x, bv0.y, bv0.z, bv0.w, bv1.x, bv1.y, bv1.z, bv1.w};
        float s = 0.f;
        float e[8];
        #pragma unroll
        for (int jj = 0; jj < 8; jj++) {
            const float A  = lo32(acc[jj]) + hi32(acc[jj]);
            const float ev = fmaf(C_LIN, P + Qs[j0 + jj], fmaf(C_ABS, A, bb[jj]));
            e[jj] = __expf(ev);
            s += e[jj];
        }
        sred[w*32 + l] = s;
        #pragma unroll
        for (int jj = 0; jj < 8; jj++)
            ws[(j0 + jj)*36 + l] = e[jj];
    }
    __syncthreads();   // B2 — Vbs dead; ws/sred complete

    // ---- overlay x[b] onto the dead Vbs region ----
    {
        float4*       xs4 = (float4*)sm;
        const float4* xg4 = (const float4*)x + b * (K_*T_/4);
        for (int idx = tid; idx < K_*T_/4; idx += 1024) xs4[idx] = xg4[idx];
    }
    __syncthreads();   // B3

    // ---- epilogue stage 1: warp = (4 i's, 64 j's); raw partials -> hred ----
    u64* hred = (u64*)(sm + HR_OFF);   // hred[(i*4 + c)*33 + l]
    {
        const int g  = w & 7;          // i-group: i = 4g..4g+3
        const int c  = w >> 3;         // j-chunk: [64c, 64c+64)
        const u64* xs2 = (const u64*)sm;
        u64 h[4] = {0ull, 0ull, 0ull, 0ull};
        const int jbeg = 64*c;
        #pragma unroll 8
        for (int j = jbeg; j < jbeg + 64; j++) {
            const u64    xv = xs2[j*32 + l];
            const float4 wq = *(const float4*)(ws + j*36 + 4*g);   // broadcast
            h[0] = fmax2p(dup2(wq.x), xv, h[0]);
            h[1] = fmax2p(dup2(wq.y), xv, h[1]);
            h[2] = fmax2p(dup2(wq.z), xv, h[2]);
            h[3] = fmax2p(dup2(wq.w), xv, h[3]);
        }
        #pragma unroll
        for (int ii = 0; ii < 4; ii++)
            hred[((4*g + ii)*4 + c)*33 + l] = h[ii];
    }
    __syncthreads();   // B4

    // ---- stage 2: warp w -> i row w; combine partials, normalize, sigmoid --
    {
        float S = sred[w];             // sred[wp*32 + i], i = w (broadcast reads)
        #pragma unroll
        for (int wp = 1; wp < 32; wp++) S += sred[wp*32 + w];
        u64 h = hred[(w*4 + 0)*33 + l];
        h = addx2(h, hred[(w*4 + 1)*33 + l]);
        h = addx2(h, hred[(w*4 + 2)*33 + l]);
        h = addx2(h, hred[(w*4 + 3)*33 + l]);
        const float inv = __fdividef(1.f, S);
        const int row = (b*K_ + igbase + w)*T_ + 2*l;
        float2 o;
        o.x = __fdividef(1.f, 1.f + __expf(-lo32(h) * inv));
        o.y = __fdividef(1.f, 1.f + __expf(-hi32(h) * inv));
        *(float2*)(out + row) = o;
    }
}

// ---------------------------------------------------------------------------
extern "C" void kernel_launch(void* const* d_in, const int* in_sizes, int n_in,
                              void* d_out, int out_size)
{
    const float* x     = (const float*)d_in[0];
    // d_in[1] = embedding (unused by the reference computation)
    const float* W     = (const float*)d_in[2];
    const float* b_lin = (const float*)d_in[3];
    const float* a     = (const float*)d_in[4];
    const float* bias  = (const float*)d_in[5];
    float* out = (float*)d_out;

    const int smemA = KA_SMEM_FLOATS * 4;   // 81216 B
    const int smemB = KB_SMEM_FLOATS * 4;   // 194688 B
    cudaFuncSetAttribute(kA, cudaFuncAttributeMaxDynamicSharedMemorySize, smemA);
    cudaFuncSetAttribute(kB, cudaFuncAttributeMaxDynamicSharedMemorySize, smemB);

    kA<<<128, 512, smemA>>>(x, W, b_lin, a);
    kB<<<dim3(8, 16), 1024, smemB>>>(x, a, bias, out);
}